// round 1
// baseline (speedup 1.0000x reference)
#include <cuda_runtime.h>
#include <cstdint>

#define PITCH   68
#define ROWS    64
#define NTHR    256
#define DIMC    128
#define KC      1024
#define SDIM    256
#define XD      8
#define ENCIN   264
#define DECIN   384

// scratch: transposed codebook [d][j] and per-code squared norms
__device__ float g_cbT[DIMC * KC];
__device__ float g_cnorm[KC];

__global__ void vq_prep(const float* __restrict__ cb) {
    int j = blockIdx.x;     // code index
    int d = threadIdx.x;    // dim (128 threads)
    float v = cb[j * DIMC + d];
    g_cbT[d * KC + j] = v;
    __shared__ float red[DIMC];
    red[d] = v * v;
    __syncthreads();
    #pragma unroll
    for (int s = 64; s > 0; s >>= 1) {
        if (d < s) red[d] += red[d + s];
        __syncthreads();
    }
    if (d == 0) g_cnorm[j] = red[0];
}

// out[c][r] = relu?( sum_k inS[k][r] * W[k][c] + bias[c] )
// thread = 8 rows x 4 cols; warp covers 8 rows x 128 cols; 8 warps -> 64 rows
__device__ __forceinline__ void gemm_tile(
    const float* __restrict__ inS, int Kdim,
    const float* __restrict__ W, const float* __restrict__ bias,
    float* __restrict__ outS, bool relu, int warp, int lane)
{
    const int r0 = warp * 8;
    const int c0 = lane * 4;
    float acc[8][4];
    #pragma unroll
    for (int i = 0; i < 8; i++) {
        acc[i][0] = 0.f; acc[i][1] = 0.f; acc[i][2] = 0.f; acc[i][3] = 0.f;
    }

    #pragma unroll 4
    for (int k = 0; k < Kdim; k++) {
        const float4 w  = *(const float4*)(W + (size_t)k * DIMC + c0);
        const float4 a0 = *(const float4*)(inS + k * PITCH + r0);
        const float4 a1 = *(const float4*)(inS + k * PITCH + r0 + 4);
        const float av[8] = {a0.x, a0.y, a0.z, a0.w, a1.x, a1.y, a1.z, a1.w};
        #pragma unroll
        for (int i = 0; i < 8; i++) {
            acc[i][0] = fmaf(av[i], w.x, acc[i][0]);
            acc[i][1] = fmaf(av[i], w.y, acc[i][1]);
            acc[i][2] = fmaf(av[i], w.z, acc[i][2]);
            acc[i][3] = fmaf(av[i], w.w, acc[i][3]);
        }
    }
    const float4 b = *(const float4*)(bias + c0);
    const float bv[4] = {b.x, b.y, b.z, b.w};
    #pragma unroll
    for (int j = 0; j < 4; j++) {
        float o[8];
        #pragma unroll
        for (int i = 0; i < 8; i++) {
            float v = acc[i][j] + bv[j];
            o[i] = relu ? fmaxf(v, 0.f) : v;
        }
        *(float4*)(outS + (c0 + j) * PITCH + r0)     = make_float4(o[0], o[1], o[2], o[3]);
        *(float4*)(outS + (c0 + j) * PITCH + r0 + 4) = make_float4(o[4], o[5], o[6], o[7]);
    }
}

__global__ void __launch_bounds__(NTHR, 1) vqvae_main(
    const float* __restrict__ state, const float* __restrict__ x,
    const float* __restrict__ cb,
    const float* __restrict__ ew1, const float* __restrict__ eb1,
    const float* __restrict__ ew2, const float* __restrict__ eb2,
    const float* __restrict__ ew3, const float* __restrict__ eb3,
    const float* __restrict__ dw1, const float* __restrict__ db1,
    const float* __restrict__ dw2, const float* __restrict__ db2,
    const float* __restrict__ dw3, const float* __restrict__ db3,
    float* __restrict__ out, int nrows)
{
    extern __shared__ float sm[];
    float* inS     = sm;                        // [DECIN][PITCH]
    float* hA      = inS + DECIN * PITCH;       // [DIMC][PITCH]
    float* hB      = hA  + DIMC * PITCH;        // [DIMC][PITCH]
    float* znorm_s = hB  + DIMC * PITCH;        // [ROWS]
    int*   idx_s   = (int*)(znorm_s + ROWS);    // [ROWS]

    const int tid  = threadIdx.x;
    const int warp = tid >> 5, lane = tid & 31;
    const int rbase = blockIdx.x * ROWS;

    // ---- load state & x, transposed into SMEM (column-major [k][r]) ----
    for (int e = tid; e < ROWS * SDIM; e += NTHR) {
        int r = e >> 8, k = e & 255;
        inS[k * PITCH + r] = state[(size_t)(rbase + r) * SDIM + k];
    }
    for (int e = tid; e < ROWS * XD; e += NTHR) {
        int r = e >> 3, k = e & 7;
        inS[(SDIM + k) * PITCH + r] = x[(size_t)(rbase + r) * XD + k];
    }
    __syncthreads();

    // ---- encoder ----
    gemm_tile(inS, ENCIN, ew1, eb1, hA, true, warp, lane);
    __syncthreads();
    gemm_tile(hA, DIMC, ew2, eb2, hB, true, warp, lane);
    __syncthreads();
    gemm_tile(hB, DIMC, ew3, eb3, hA, false, warp, lane);   // z_e -> hA
    __syncthreads();

    // ---- |z_e|^2 per row ----
    if (tid < ROWS) {
        float s = 0.f;
        #pragma unroll 4
        for (int d = 0; d < DIMC; d++) {
            float z = hA[d * PITCH + tid];
            s = fmaf(z, z, s);
        }
        znorm_s[tid] = s;
    }
    __syncthreads();

    // ---- VQ: argmin_k (znorm - 2*dot + cnorm), first-index tie break ----
    const int r0 = warp * 8;
    unsigned long long best[8];
    #pragma unroll
    for (int i = 0; i < 8; i++) best[i] = ~0ull;

    for (int pass = 0; pass < 8; pass++) {
        const int j0 = pass * 128 + lane * 4;
        float acc[8][4];
        #pragma unroll
        for (int i = 0; i < 8; i++) {
            acc[i][0] = 0.f; acc[i][1] = 0.f; acc[i][2] = 0.f; acc[i][3] = 0.f;
        }
        #pragma unroll 4
        for (int d = 0; d < DIMC; d++) {
            const float4 w  = *(const float4*)(g_cbT + d * KC + j0);
            const float4 a0 = *(const float4*)(hA + d * PITCH + r0);
            const float4 a1 = *(const float4*)(hA + d * PITCH + r0 + 4);
            const float av[8] = {a0.x, a0.y, a0.z, a0.w, a1.x, a1.y, a1.z, a1.w};
            #pragma unroll
            for (int i = 0; i < 8; i++) {
                acc[i][0] = fmaf(av[i], w.x, acc[i][0]);
                acc[i][1] = fmaf(av[i], w.y, acc[i][1]);
                acc[i][2] = fmaf(av[i], w.z, acc[i][2]);
                acc[i][3] = fmaf(av[i], w.w, acc[i][3]);
            }
        }
        const float4 cn4 = *(const float4*)(g_cnorm + j0);
        const float cn[4] = {cn4.x, cn4.y, cn4.z, cn4.w};
        #pragma unroll
        for (int i = 0; i < 8; i++) {
            const float zn = znorm_s[r0 + i];
            #pragma unroll
            for (int jj = 0; jj < 4; jj++) {
                float dv = (zn - 2.f * acc[i][jj]) + cn[jj];   // same assoc as reference
                unsigned u = __float_as_uint(dv);
                u = (u & 0x80000000u) ? ~u : (u | 0x80000000u); // order-preserving map
                unsigned long long key =
                    ((unsigned long long)u << 32) | (unsigned)(j0 + jj);
                if (key < best[i]) best[i] = key;
            }
        }
    }
    #pragma unroll
    for (int off = 16; off > 0; off >>= 1) {
        #pragma unroll
        for (int i = 0; i < 8; i++) {
            unsigned long long o = __shfl_xor_sync(0xFFFFFFFFu, best[i], off);
            if (o < best[i]) best[i] = o;
        }
    }
    if (lane == 0) {
        #pragma unroll
        for (int i = 0; i < 8; i++)
            idx_s[r0 + i] = (int)(best[i] & 0xFFFFFFFFull);
    }
    __syncthreads();

    // ---- outputs (z_e, z_q, indices) + build decoder input (state ++ z_q_st) ----
    const size_t B = (size_t)nrows;
    float* out_xt = out;                          // [B,8]
    float* out_ze = out + B * XD;                 // [B,128]
    float* out_zq = out_ze + B * (size_t)DIMC;    // [B,128]
    float* out_id = out_zq + B * (size_t)DIMC;    // [B]

    for (int e = tid; e < ROWS * DIMC; e += NTHR) {
        int r = e >> 7, d = e & 127;
        float z = hA[d * PITCH + r];
        float q = cb[(size_t)idx_s[r] * DIMC + d];
        out_ze[(size_t)(rbase + r) * DIMC + d] = z;
        out_zq[(size_t)(rbase + r) * DIMC + d] = q;
        inS[(SDIM + d) * PITCH + r] = z + (q - z);   // straight-through, ref rounding
    }
    if (tid < ROWS) out_id[rbase + tid] = (float)idx_s[tid];
    __syncthreads();

    // ---- decoder ----
    gemm_tile(inS, DECIN, dw1, db1, hA, true, warp, lane);
    __syncthreads();
    gemm_tile(hA, DIMC, dw2, db2, hB, true, warp, lane);
    __syncthreads();

    // final layer: [64 rows][8 cols], thread = (row, 2 cols)
    {
        int r  = tid & 63;
        int cg = tid >> 6;       // 0..3
        int c  = cg * 2;
        float a0 = 0.f, a1 = 0.f;
        #pragma unroll 4
        for (int d = 0; d < DIMC; d++) {
            float h = hB[d * PITCH + r];
            a0 = fmaf(h, dw3[d * XD + c],     a0);
            a1 = fmaf(h, dw3[d * XD + c + 1], a1);
        }
        out_xt[(size_t)(rbase + r) * XD + c]     = a0 + db3[c];
        out_xt[(size_t)(rbase + r) * XD + c + 1] = a1 + db3[c + 1];
    }
}

extern "C" void kernel_launch(void* const* d_in, const int* in_sizes, int n_in,
                              void* d_out, int out_size) {
    const float* state = (const float*)d_in[0];
    const float* x     = (const float*)d_in[1];
    const float* cb    = (const float*)d_in[2];
    const float* ew1   = (const float*)d_in[3];
    const float* eb1   = (const float*)d_in[4];
    const float* ew2   = (const float*)d_in[5];
    const float* eb2   = (const float*)d_in[6];
    const float* ew3   = (const float*)d_in[7];
    const float* eb3   = (const float*)d_in[8];
    const float* dw1   = (const float*)d_in[9];
    const float* db1   = (const float*)d_in[10];
    const float* dw2   = (const float*)d_in[11];
    const float* db2   = (const float*)d_in[12];
    const float* dw3   = (const float*)d_in[13];
    const float* db3   = (const float*)d_in[14];

    const int nrows = in_sizes[0] / SDIM;   // 262144

    vq_prep<<<KC, DIMC>>>(cb);

    size_t smemBytes =
        (size_t)(DECIN * PITCH + 2 * DIMC * PITCH + ROWS) * sizeof(float)
        + ROWS * sizeof(int);
    cudaFuncSetAttribute((const void*)vqvae_main,
                         cudaFuncAttributeMaxDynamicSharedMemorySize,
                         (int)smemBytes);

    vqvae_main<<<nrows / ROWS, NTHR, smemBytes>>>(
        state, x, cb, ew1, eb1, ew2, eb2, ew3, eb3,
        dw1, db1, dw2, db2, dw3, db3,
        (float*)d_out, nrows);
}

// round 2
// speedup vs baseline: 1.0832x; 1.0832x over previous
#include <cuda_runtime.h>
#include <cstdint>

#define PITCH   68
#define ROWS    64
#define NTHR    256
#define DIMC    128
#define KC      1024
#define SDIM    256
#define XD      8
#define ENCIN   264
#define DECIN   384

typedef unsigned long long u64;

// scratch: transposed codebook [d][j] and per-code squared norms
__device__ float g_cbT[DIMC * KC];
__device__ float g_cnorm[KC];

__global__ void vq_prep(const float* __restrict__ cb) {
    int j = blockIdx.x;     // code index
    int d = threadIdx.x;    // dim (128 threads)
    float v = cb[j * DIMC + d];
    g_cbT[d * KC + j] = v;
    __shared__ float red[DIMC];
    red[d] = v * v;
    __syncthreads();
    #pragma unroll
    for (int s = 64; s > 0; s >>= 1) {
        if (d < s) red[d] += red[d + s];
        __syncthreads();
    }
    if (d == 0) g_cnorm[j] = red[0];
}

// ---- packed f32x2 helpers (Blackwell FFMA2) ----
__device__ __forceinline__ u64 dup2(float w) {
    u64 r; unsigned u = __float_as_uint(w);
    asm("mov.b64 %0, {%1, %1};" : "=l"(r) : "r"(u));
    return r;
}
__device__ __forceinline__ void ffma2(u64& d, u64 a, u64 b) {
    asm("fma.rn.f32x2 %0, %1, %2, %0;" : "+l"(d) : "l"(a), "l"(b));
}
__device__ __forceinline__ float2 unpk(u64 v) {
    unsigned lo, hi;
    asm("mov.b64 {%0, %1}, %2;" : "=r"(lo), "=r"(hi) : "l"(v));
    return make_float2(__uint_as_float(lo), __uint_as_float(hi));
}

// out[c][r] = relu?( sum_k inS[k][r] * W[k][c] + bias[c] )
// thread = 8 rows x 4 cols via 4 row-pairs (f32x2); warp covers 8 rows x 128 cols.
__device__ __forceinline__ void gemm_tile(
    const float* __restrict__ inS, int Kdim,
    const float* __restrict__ W, const float* __restrict__ bias,
    float* __restrict__ outS, bool relu, int warp, int lane)
{
    const int r0 = warp * 8;
    const int c0 = lane * 4;
    u64 acc[4][4];
    #pragma unroll
    for (int i = 0; i < 4; i++)
        #pragma unroll
        for (int j = 0; j < 4; j++) acc[i][j] = 0ull;

    #pragma unroll 4
    for (int k = 0; k < Kdim; k++) {
        const ulonglong2 aA = *(const ulonglong2*)(inS + k * PITCH + r0);
        const ulonglong2 aB = *(const ulonglong2*)(inS + k * PITCH + r0 + 4);
        const float4 w = *(const float4*)(W + (size_t)k * DIMC + c0);
        const u64 wd[4] = {dup2(w.x), dup2(w.y), dup2(w.z), dup2(w.w)};
        const u64 av[4] = {aA.x, aA.y, aB.x, aB.y};
        #pragma unroll
        for (int i = 0; i < 4; i++) {
            ffma2(acc[i][0], av[i], wd[0]);
            ffma2(acc[i][1], av[i], wd[1]);
            ffma2(acc[i][2], av[i], wd[2]);
            ffma2(acc[i][3], av[i], wd[3]);
        }
    }
    const float4 b = *(const float4*)(bias + c0);
    const float bv[4] = {b.x, b.y, b.z, b.w};
    #pragma unroll
    for (int j = 0; j < 4; j++) {
        float o[8];
        #pragma unroll
        for (int i = 0; i < 4; i++) {
            float2 p = unpk(acc[i][j]);
            float v0 = p.x + bv[j];
            float v1 = p.y + bv[j];
            o[2 * i]     = relu ? fmaxf(v0, 0.f) : v0;
            o[2 * i + 1] = relu ? fmaxf(v1, 0.f) : v1;
        }
        *(float4*)(outS + (c0 + j) * PITCH + r0)     = make_float4(o[0], o[1], o[2], o[3]);
        *(float4*)(outS + (c0 + j) * PITCH + r0 + 4) = make_float4(o[4], o[5], o[6], o[7]);
    }
}

__global__ void __launch_bounds__(NTHR, 1) vqvae_main(
    const float* __restrict__ state, const float* __restrict__ x,
    const float* __restrict__ cb,
    const float* __restrict__ ew1, const float* __restrict__ eb1,
    const float* __restrict__ ew2, const float* __restrict__ eb2,
    const float* __restrict__ ew3, const float* __restrict__ eb3,
    const float* __restrict__ dw1, const float* __restrict__ db1,
    const float* __restrict__ dw2, const float* __restrict__ db2,
    const float* __restrict__ dw3, const float* __restrict__ db3,
    float* __restrict__ out, int nrows)
{
    extern __shared__ float sm[];
    float* inS     = sm;                        // [DECIN][PITCH]
    float* hA      = inS + DECIN * PITCH;       // [DIMC][PITCH]
    float* hB      = hA  + DIMC * PITCH;        // [DIMC][PITCH]
    float* znorm_s = hB  + DIMC * PITCH;        // [ROWS]
    int*   idx_s   = (int*)(znorm_s + ROWS);    // [ROWS]

    const int tid  = threadIdx.x;
    const int warp = tid >> 5, lane = tid & 31;
    const int rbase = blockIdx.x * ROWS;

    // ---- load state & x, transposed into SMEM (column-major [k][r]) ----
    for (int e = tid; e < ROWS * SDIM; e += NTHR) {
        int r = e >> 8, k = e & 255;
        inS[k * PITCH + r] = state[(size_t)(rbase + r) * SDIM + k];
    }
    for (int e = tid; e < ROWS * XD; e += NTHR) {
        int r = e >> 3, k = e & 7;
        inS[(SDIM + k) * PITCH + r] = x[(size_t)(rbase + r) * XD + k];
    }
    __syncthreads();

    // ---- encoder ----
    gemm_tile(inS, ENCIN, ew1, eb1, hA, true, warp, lane);
    __syncthreads();
    gemm_tile(hA, DIMC, ew2, eb2, hB, true, warp, lane);
    __syncthreads();
    gemm_tile(hB, DIMC, ew3, eb3, hA, false, warp, lane);   // z_e -> hA
    __syncthreads();

    // ---- |z_e|^2 per row ----
    if (tid < ROWS) {
        float s = 0.f;
        #pragma unroll 4
        for (int d = 0; d < DIMC; d++) {
            float z = hA[d * PITCH + tid];
            s = fmaf(z, z, s);
        }
        znorm_s[tid] = s;
    }
    __syncthreads();

    // ---- VQ: argmin_k (znorm - 2*dot + cnorm), first-index tie break ----
    const int r0 = warp * 8;
    u64 best[8];
    #pragma unroll
    for (int i = 0; i < 8; i++) best[i] = ~0ull;

    for (int pass = 0; pass < 8; pass++) {
        const int j0 = pass * 128 + lane * 4;
        u64 acc[4][4];
        #pragma unroll
        for (int i = 0; i < 4; i++)
            #pragma unroll
            for (int j = 0; j < 4; j++) acc[i][j] = 0ull;

        #pragma unroll 4
        for (int d = 0; d < DIMC; d++) {
            const ulonglong2 aA = *(const ulonglong2*)(hA + d * PITCH + r0);
            const ulonglong2 aB = *(const ulonglong2*)(hA + d * PITCH + r0 + 4);
            const float4 w = *(const float4*)(g_cbT + d * KC + j0);
            const u64 wd[4] = {dup2(w.x), dup2(w.y), dup2(w.z), dup2(w.w)};
            const u64 av[4] = {aA.x, aA.y, aB.x, aB.y};
            #pragma unroll
            for (int i = 0; i < 4; i++) {
                ffma2(acc[i][0], av[i], wd[0]);
                ffma2(acc[i][1], av[i], wd[1]);
                ffma2(acc[i][2], av[i], wd[2]);
                ffma2(acc[i][3], av[i], wd[3]);
            }
        }
        const float4 cn4 = *(const float4*)(g_cnorm + j0);
        const float cn[4] = {cn4.x, cn4.y, cn4.z, cn4.w};
        #pragma unroll
        for (int i = 0; i < 4; i++) {
            const float zn0 = znorm_s[r0 + 2 * i];
            const float zn1 = znorm_s[r0 + 2 * i + 1];
            #pragma unroll
            for (int jj = 0; jj < 4; jj++) {
                float2 p = unpk(acc[i][jj]);
                float dv0 = (zn0 - 2.f * p.x) + cn[jj];   // same assoc as reference
                float dv1 = (zn1 - 2.f * p.y) + cn[jj];
                unsigned u0 = __float_as_uint(dv0);
                u0 = (u0 & 0x80000000u) ? ~u0 : (u0 | 0x80000000u);
                unsigned u1 = __float_as_uint(dv1);
                u1 = (u1 & 0x80000000u) ? ~u1 : (u1 | 0x80000000u);
                u64 k0 = ((u64)u0 << 32) | (unsigned)(j0 + jj);
                u64 k1 = ((u64)u1 << 32) | (unsigned)(j0 + jj);
                if (k0 < best[2 * i])     best[2 * i]     = k0;
                if (k1 < best[2 * i + 1]) best[2 * i + 1] = k1;
            }
        }
    }
    #pragma unroll
    for (int off = 16; off > 0; off >>= 1) {
        #pragma unroll
        for (int i = 0; i < 8; i++) {
            u64 o = __shfl_xor_sync(0xFFFFFFFFu, best[i], off);
            if (o < best[i]) best[i] = o;
        }
    }
    if (lane == 0) {
        #pragma unroll
        for (int i = 0; i < 8; i++)
            idx_s[r0 + i] = (int)(best[i] & 0xFFFFFFFFull);
    }
    __syncthreads();

    // ---- outputs (z_e, z_q, indices) + build decoder input (state ++ z_q_st) ----
    const size_t B = (size_t)nrows;
    float* out_xt = out;                          // [B,8]
    float* out_ze = out + B * XD;                 // [B,128]
    float* out_zq = out_ze + B * (size_t)DIMC;    // [B,128]
    float* out_id = out_zq + B * (size_t)DIMC;    // [B]

    for (int e = tid; e < ROWS * DIMC; e += NTHR) {
        int r = e >> 7, d = e & 127;
        float z = hA[d * PITCH + r];
        float q = cb[(size_t)idx_s[r] * DIMC + d];
        out_ze[(size_t)(rbase + r) * DIMC + d] = z;
        out_zq[(size_t)(rbase + r) * DIMC + d] = q;
        inS[(SDIM + d) * PITCH + r] = z + (q - z);   // straight-through, ref rounding
    }
    if (tid < ROWS) out_id[rbase + tid] = (float)idx_s[tid];
    __syncthreads();

    // ---- decoder ----
    gemm_tile(inS, DECIN, dw1, db1, hA, true, warp, lane);
    __syncthreads();
    gemm_tile(hA, DIMC, dw2, db2, hB, true, warp, lane);
    __syncthreads();

    // final layer: [64 rows][8 cols], thread = (row, 2 cols)
    {
        int r  = tid & 63;
        int cg = tid >> 6;       // 0..3
        int c  = cg * 2;
        float a0 = 0.f, a1 = 0.f;
        #pragma unroll 4
        for (int d = 0; d < DIMC; d++) {
            float h = hB[d * PITCH + r];
            a0 = fmaf(h, dw3[d * XD + c],     a0);
            a1 = fmaf(h, dw3[d * XD + c + 1], a1);
        }
        out_xt[(size_t)(rbase + r) * XD + c]     = a0 + db3[c];
        out_xt[(size_t)(rbase + r) * XD + c + 1] = a1 + db3[c + 1];
    }
}

extern "C" void kernel_launch(void* const* d_in, const int* in_sizes, int n_in,
                              void* d_out, int out_size) {
    const float* state = (const float*)d_in[0];
    const float* x     = (const float*)d_in[1];
    const float* cb    = (const float*)d_in[2];
    const float* ew1   = (const float*)d_in[3];
    const float* eb1   = (const float*)d_in[4];
    const float* ew2   = (const float*)d_in[5];
    const float* eb2   = (const float*)d_in[6];
    const float* ew3   = (const float*)d_in[7];
    const float* eb3   = (const float*)d_in[8];
    const float* dw1   = (const float*)d_in[9];
    const float* db1   = (const float*)d_in[10];
    const float* dw2   = (const float*)d_in[11];
    const float* db2   = (const float*)d_in[12];
    const float* dw3   = (const float*)d_in[13];
    const float* db3   = (const float*)d_in[14];

    const int nrows = in_sizes[0] / SDIM;   // 262144

    vq_prep<<<KC, DIMC>>>(cb);

    size_t smemBytes =
        (size_t)(DECIN * PITCH + 2 * DIMC * PITCH + ROWS) * sizeof(float)
        + ROWS * sizeof(int);
    cudaFuncSetAttribute((const void*)vqvae_main,
                         cudaFuncAttributeMaxDynamicSharedMemorySize,
                         (int)smemBytes);

    vqvae_main<<<nrows / ROWS, NTHR, smemBytes>>>(
        state, x, cb, ew1, eb1, ew2, eb2, ew3, eb3,
        dw1, db1, dw2, db2, dw3, db3,
        (float*)d_out, nrows);
}

// round 4
// speedup vs baseline: 1.1655x; 1.0760x over previous
#include <cuda_runtime.h>
#include <cuda_bf16.h>
#include <cstdint>

typedef unsigned long long u64;
typedef unsigned int u32;

#define PITCH   68
#define ROWS    64
#define NTHR    256
#define DIMC    128
#define KC      1024
#define SDIM    256
#define XD      8
#define ENCIN   264
#define DECIN   384
#define BTOT    262144

#define VROWS   128
#define VTHR    512
#define NCHUNK  8
#define CHN     128
#define CAND_MAX 32
#define APW     68          // u32 words per SMEM tile row (136 bf16 = 272B)

// ---------------- scratch globals ----------------
__device__ float          g_cnorm[KC];
__device__ __nv_bfloat16  g_cbh[KC * DIMC];
__device__ __nv_bfloat16  g_cbl[KC * DIMC];
__device__ float          g_ze[(size_t)BTOT * DIMC];
__device__ float          g_znorm[BTOT];
__device__ float          g_zabs[BTOT];
__device__ int            g_idx[BTOT];

// ---------------- prep: cnorm (fp32) + codebook bf16 split ----------------
__global__ void vq_prep(const float* __restrict__ cb) {
    int j = blockIdx.x;
    int d = threadIdx.x;
    float v = cb[j * DIMC + d];
    __nv_bfloat16 h = __float2bfloat16(v);
    g_cbh[j * DIMC + d] = h;
    g_cbl[j * DIMC + d] = __float2bfloat16(v - __bfloat162float(h));
    __shared__ float red[DIMC];
    red[d] = v * v;
    __syncthreads();
    #pragma unroll
    for (int s = 64; s > 0; s >>= 1) {
        if (d < s) red[d] += red[d + s];
        __syncthreads();
    }
    if (d == 0) g_cnorm[j] = red[0];
}

// ---------------- packed f32x2 helpers ----------------
__device__ __forceinline__ u64 dup2(float w) {
    u64 r; unsigned u = __float_as_uint(w);
    asm("mov.b64 %0, {%1, %1};" : "=l"(r) : "r"(u));
    return r;
}
__device__ __forceinline__ void ffma2(u64& d, u64 a, u64 b) {
    asm("fma.rn.f32x2 %0, %1, %2, %0;" : "+l"(d) : "l"(a), "l"(b));
}
__device__ __forceinline__ float2 unpk(u64 v) {
    unsigned lo, hi;
    asm("mov.b64 {%0, %1}, %2;" : "=r"(lo), "=r"(hi) : "l"(v));
    return make_float2(__uint_as_float(lo), __uint_as_float(hi));
}

// ---------------- fp32 gemm tile (proven R2) ----------------
__device__ __forceinline__ void gemm_tile(
    const float* __restrict__ inS, int Kdim,
    const float* __restrict__ W, const float* __restrict__ bias,
    float* __restrict__ outS, bool relu, int warp, int lane)
{
    const int r0 = warp * 8;
    const int c0 = lane * 4;
    u64 acc[4][4];
    #pragma unroll
    for (int i = 0; i < 4; i++)
        #pragma unroll
        for (int j = 0; j < 4; j++) acc[i][j] = 0ull;

    #pragma unroll 4
    for (int k = 0; k < Kdim; k++) {
        const ulonglong2 aA = *(const ulonglong2*)(inS + k * PITCH + r0);
        const ulonglong2 aB = *(const ulonglong2*)(inS + k * PITCH + r0 + 4);
        const float4 w = *(const float4*)(W + (size_t)k * DIMC + c0);
        const u64 wd[4] = {dup2(w.x), dup2(w.y), dup2(w.z), dup2(w.w)};
        const u64 av[4] = {aA.x, aA.y, aB.x, aB.y};
        #pragma unroll
        for (int i = 0; i < 4; i++) {
            ffma2(acc[i][0], av[i], wd[0]);
            ffma2(acc[i][1], av[i], wd[1]);
            ffma2(acc[i][2], av[i], wd[2]);
            ffma2(acc[i][3], av[i], wd[3]);
        }
    }
    const float4 b = *(const float4*)(bias + c0);
    const float bv[4] = {b.x, b.y, b.z, b.w};
    #pragma unroll
    for (int j = 0; j < 4; j++) {
        float o[8];
        #pragma unroll
        for (int i = 0; i < 4; i++) {
            float2 p = unpk(acc[i][j]);
            float v0 = p.x + bv[j];
            float v1 = p.y + bv[j];
            o[2 * i]     = relu ? fmaxf(v0, 0.f) : v0;
            o[2 * i + 1] = relu ? fmaxf(v1, 0.f) : v1;
        }
        *(float4*)(outS + (c0 + j) * PITCH + r0)     = make_float4(o[0], o[1], o[2], o[3]);
        *(float4*)(outS + (c0 + j) * PITCH + r0 + 4) = make_float4(o[4], o[5], o[6], o[7]);
    }
}

// ---------------- encoder ----------------
__global__ void __launch_bounds__(NTHR, 1) enc_kernel(
    const float* __restrict__ state, const float* __restrict__ x,
    const float* __restrict__ ew1, const float* __restrict__ eb1,
    const float* __restrict__ ew2, const float* __restrict__ eb2,
    const float* __restrict__ ew3, const float* __restrict__ eb3,
    float* __restrict__ out, int nrows)
{
    extern __shared__ float sm[];
    float* inS = sm;                         // [ENCIN][PITCH]
    float* hA  = inS + ENCIN * PITCH;
    float* hB  = hA  + DIMC * PITCH;

    const int tid  = threadIdx.x;
    const int warp = tid >> 5, lane = tid & 31;
    const int rbase = blockIdx.x * ROWS;

    for (int e = tid; e < ROWS * SDIM; e += NTHR) {
        int r = e >> 8, k = e & 255;
        inS[k * PITCH + r] = state[(size_t)(rbase + r) * SDIM + k];
    }
    for (int e = tid; e < ROWS * XD; e += NTHR) {
        int r = e >> 3, k = e & 7;
        inS[(SDIM + k) * PITCH + r] = x[(size_t)(rbase + r) * XD + k];
    }
    __syncthreads();

    gemm_tile(inS, ENCIN, ew1, eb1, hA, true, warp, lane);
    __syncthreads();
    gemm_tile(hA, DIMC, ew2, eb2, hB, true, warp, lane);
    __syncthreads();
    gemm_tile(hB, DIMC, ew3, eb3, hA, false, warp, lane);  // z_e -> hA
    __syncthreads();

    if (tid < ROWS) {
        float s = 0.f, a = 0.f;
        #pragma unroll 4
        for (int d = 0; d < DIMC; d++) {
            float z = hA[d * PITCH + tid];
            s = fmaf(z, z, s);
            a += fabsf(z);
        }
        g_znorm[rbase + tid] = s;
        g_zabs[rbase + tid]  = a;
    }

    const size_t B = (size_t)nrows;
    float* out_ze = out + B * XD;
    for (int e = tid; e < ROWS * DIMC; e += NTHR) {
        int r = e >> 7, d = e & 127;
        float z = hA[d * PITCH + r];
        out_ze[(size_t)(rbase + r) * DIMC + d] = z;
        g_ze[(size_t)(rbase + r) * DIMC + d]   = z;
    }
}

// ---------------- mma.sync helper (bf16, f32 accum, m16n8k16) ----------------
__device__ __forceinline__ void mma16816(float* d, u32 a0, u32 a1, u32 a2, u32 a3,
                                         u32 b0, u32 b1) {
    asm volatile(
        "mma.sync.aligned.m16n8k16.row.col.f32.bf16.bf16.f32 "
        "{%0,%1,%2,%3}, {%4,%5,%6,%7}, {%8,%9}, {%0,%1,%2,%3};"
        : "+f"(d[0]), "+f"(d[1]), "+f"(d[2]), "+f"(d[3])
        : "r"(a0), "r"(a1), "r"(a2), "r"(a3), "r"(b0), "r"(b1));
}

__device__ __forceinline__ u32 fmap(float f) {
    u32 u = __float_as_uint(f);
    return (u & 0x80000000u) ? ~u : (u | 0x80000000u);
}
__device__ __forceinline__ float finv(u32 m) {
    u32 u = (m & 0x80000000u) ? (m ^ 0x80000000u) : ~m;
    return __uint_as_float(u);
}

// ---------------- VQ kernel (mma.sync bf16 split + exact fp32 refine) ----------
// smem layout (byte offsets):
//   0:      finalS  u64[128]     (1024)
//   1024:   cnS     f32[1024]    (4096)
//   5120:   margS   f32[128]     (512)
//   5632:   bestU   u32[128]     (512)
//   6144:   cntS    u32[128]     (512)
//   6656:   candS   u32[128*32]  (16384)
//   23040:  zhS     u32[128*68]  (34816)
//   57856:  zlS     u32[128*68]  (34816)
//   92672:  chS     u32[128*68]  (34816)
//   127488: clS     u32[128*68]  (34816)
#define VQ_SMEM 162304

__global__ void __launch_bounds__(VTHR, 1) vq_kernel(
    const float* __restrict__ cb, float* __restrict__ out, int nrows)
{
    extern __shared__ char smc[];
    u64*   finalS = (u64*)(smc);
    float* cnS    = (float*)(smc + 1024);
    float* margS  = (float*)(smc + 5120);
    u32*   bestU  = (u32*)(smc + 5632);
    u32*   cntS   = (u32*)(smc + 6144);
    u32*   candS  = (u32*)(smc + 6656);
    u32*   zhS    = (u32*)(smc + 23040);
    u32*   zlS    = (u32*)(smc + 57856);
    u32*   chS    = (u32*)(smc + 92672);
    u32*   clS    = (u32*)(smc + 127488);

    const int tid  = threadIdx.x;
    const int wid  = tid >> 5, lane = tid & 31;
    const int g    = lane >> 2, tg = lane & 3;
    const int rbase = blockIdx.x * VROWS;

    // warp tiling: 16 warps = 8 M-tiles x 2 N-halves
    const int mbase = (wid >> 1) * 16;
    const int nhalf = (wid & 1) * 64;

    // ---- init + stage cnorm / margins ----
    for (int i = tid; i < KC; i += VTHR) cnS[i] = g_cnorm[i];
    for (int i = tid; i < VROWS; i += VTHR) {
        bestU[i]  = 0xFFFFFFFFu;
        finalS[i] = ~0ull;
        cntS[i]   = 0u;
        margS[i]  = g_zabs[rbase + i] * 1.0e-6f + 1.0e-6f;
    }

    // ---- stage A: z_e -> (zh, zl) bf16 pairs, pitch 68 words ----
    for (int i = tid; i < VROWS * 64; i += VTHR) {
        int r = i >> 6, c = i & 63;           // c = d/2
        float2 z = *(const float2*)(g_ze + (size_t)(rbase + r) * DIMC + c * 2);
        __nv_bfloat16 h0 = __float2bfloat16(z.x);
        __nv_bfloat16 h1 = __float2bfloat16(z.y);
        __nv_bfloat16 l0 = __float2bfloat16(z.x - __bfloat162float(h0));
        __nv_bfloat16 l1 = __float2bfloat16(z.y - __bfloat162float(h1));
        __nv_bfloat162 hp(h0, h1), lp(l0, l1);
        zhS[r * APW + c] = *(u32*)&hp;
        zlS[r * APW + c] = *(u32*)&lp;
    }
    __syncthreads();

    float dacc[8][4];

    for (int q = 0; q < NCHUNK; q++) {
        // ---- stage B chunk (128 codes), uint4 copies ----
        {
            const uint4* srcH = (const uint4*)(g_cbh + (size_t)q * CHN * DIMC);
            const uint4* srcL = (const uint4*)(g_cbl + (size_t)q * CHN * DIMC);
            for (int i = tid; i < CHN * 16; i += VTHR) {   // 16 uint4 per code row
                int r = i >> 4, c4 = (i & 15) * 4;
                *(uint4*)(chS + r * APW + c4) = srcH[i];
                *(uint4*)(clS + r * APW + c4) = srcL[i];
            }
        }
        __syncthreads();

        #pragma unroll
        for (int nt = 0; nt < 8; nt++) {
            dacc[nt][0] = 0.f; dacc[nt][1] = 0.f; dacc[nt][2] = 0.f; dacc[nt][3] = 0.f;
        }

        // pass 1: zh * ch + zh * cl
        #pragma unroll
        for (int kt = 0; kt < 8; kt++) {
            const int ka = kt * 8 + tg;
            const u32 a0 = zhS[(mbase + g)     * APW + ka];
            const u32 a1 = zhS[(mbase + g + 8) * APW + ka];
            const u32 a2 = zhS[(mbase + g)     * APW + ka + 4];
            const u32 a3 = zhS[(mbase + g + 8) * APW + ka + 4];
            #pragma unroll
            for (int nt = 0; nt < 8; nt++) {
                const int w = (nhalf + nt * 8 + g) * APW + ka;
                mma16816(dacc[nt], a0, a1, a2, a3, chS[w], chS[w + 4]);
                mma16816(dacc[nt], a0, a1, a2, a3, clS[w], clS[w + 4]);
            }
        }
        // pass 2: zl * ch
        #pragma unroll
        for (int kt = 0; kt < 8; kt++) {
            const int ka = kt * 8 + tg;
            const u32 a0 = zlS[(mbase + g)     * APW + ka];
            const u32 a1 = zlS[(mbase + g + 8) * APW + ka];
            const u32 a2 = zlS[(mbase + g)     * APW + ka + 4];
            const u32 a3 = zlS[(mbase + g + 8) * APW + ka + 4];
            #pragma unroll
            for (int nt = 0; nt < 8; nt++) {
                const int w = (nhalf + nt * 8 + g) * APW + ka;
                mma16816(dacc[nt], a0, a1, a2, a3, chS[w], chS[w + 4]);
            }
        }

        // ---- epilogue: dist = cnorm - 2*dot; running min + candidates ----
        const int r1 = mbase + g, r2 = r1 + 8;
        u32 min1 = 0xFFFFFFFFu, min2 = 0xFFFFFFFFu;
        #pragma unroll
        for (int nt = 0; nt < 8; nt++) {
            const int jb = q * CHN + nhalf + nt * 8 + 2 * tg;
            float s0 = cnS[jb]     - 2.f * dacc[nt][0];
            float s1 = cnS[jb + 1] - 2.f * dacc[nt][1];
            float s2 = cnS[jb]     - 2.f * dacc[nt][2];
            float s3 = cnS[jb + 1] - 2.f * dacc[nt][3];
            dacc[nt][0] = s0; dacc[nt][1] = s1; dacc[nt][2] = s2; dacc[nt][3] = s3;
            u32 m0 = fmap(s0), m1 = fmap(s1), m2 = fmap(s2), m3 = fmap(s3);
            min1 = min(min1, min(m0, m1));
            min2 = min(min2, min(m2, m3));
        }
        atomicMin(&bestU[r1], min1);
        atomicMin(&bestU[r2], min2);
        __syncthreads();

        const float thr1 = finv(bestU[r1]) + margS[r1];
        const float thr2 = finv(bestU[r2]) + margS[r2];
        #pragma unroll
        for (int nt = 0; nt < 8; nt++) {
            const int jb = q * CHN + nhalf + nt * 8 + 2 * tg;
            if (dacc[nt][0] <= thr1) {
                u32 p = atomicAdd(&cntS[r1], 1u);
                if (p < CAND_MAX) candS[r1 * CAND_MAX + p] = (u32)jb;
            }
            if (dacc[nt][1] <= thr1) {
                u32 p = atomicAdd(&cntS[r1], 1u);
                if (p < CAND_MAX) candS[r1 * CAND_MAX + p] = (u32)(jb + 1);
            }
            if (dacc[nt][2] <= thr2) {
                u32 p = atomicAdd(&cntS[r2], 1u);
                if (p < CAND_MAX) candS[r2 * CAND_MAX + p] = (u32)jb;
            }
            if (dacc[nt][3] <= thr2) {
                u32 p = atomicAdd(&cntS[r2], 1u);
                if (p < CAND_MAX) candS[r2 * CAND_MAX + p] = (u32)(jb + 1);
            }
        }
        __syncthreads();
    }

    // ---- exact fp32 refine: 4 threads per row, reference order ----
    {
        const int rr = tid >> 2, c4 = tid & 3;
        const float zn = g_znorm[rbase + rr];
        const float* zp = g_ze + (size_t)(rbase + rr) * DIMC;
        int cnt = (int)cntS[rr];
        if (cnt > CAND_MAX) cnt = CAND_MAX;
        for (int c = c4; c < cnt; c += 4) {
            int j = (int)candS[rr * CAND_MAX + c];
            const float* cp = cb + (size_t)j * DIMC;
            float dot = 0.f;
            #pragma unroll 8
            for (int d = 0; d < DIMC; d++) dot = fmaf(zp[d], cp[d], dot);
            float dvv = (zn - 2.0f * dot) + cnS[j];
            u64 key = ((u64)fmap(dvv) << 32) | (u32)j;
            atomicMin(&finalS[rr], key);
        }
    }
    __syncthreads();

    if (tid < VROWS) {
        int idx = (int)(finalS[tid] & 0xFFFFFFFFull);
        g_idx[rbase + tid] = idx;
        float* out_id = out + (size_t)nrows * XD + (size_t)nrows * DIMC * 2;
        out_id[rbase + tid] = (float)idx;
    }
}

// ---------------- decoder ----------------
__global__ void __launch_bounds__(NTHR, 1) dec_kernel(
    const float* __restrict__ state, const float* __restrict__ cb,
    const float* __restrict__ dw1, const float* __restrict__ db1,
    const float* __restrict__ dw2, const float* __restrict__ db2,
    const float* __restrict__ dw3, const float* __restrict__ db3,
    float* __restrict__ out, int nrows)
{
    extern __shared__ float sm[];
    float* inS = sm;                        // [DECIN][PITCH]
    float* hA  = inS + DECIN * PITCH;
    float* hB  = hA  + DIMC * PITCH;

    const int tid  = threadIdx.x;
    const int warp = tid >> 5, lane = tid & 31;
    const int rbase = blockIdx.x * ROWS;

    const size_t B = (size_t)nrows;
    float* out_xt = out;
    float* out_zq = out + B * XD + B * (size_t)DIMC;

    for (int e = tid; e < ROWS * SDIM; e += NTHR) {
        int r = e >> 8, k = e & 255;
        inS[k * PITCH + r] = state[(size_t)(rbase + r) * SDIM + k];
    }
    for (int e = tid; e < ROWS * DIMC; e += NTHR) {
        int r = e >> 7, d = e & 127;
        float z = g_ze[(size_t)(rbase + r) * DIMC + d];
        float q = cb[(size_t)g_idx[rbase + r] * DIMC + d];
        out_zq[(size_t)(rbase + r) * DIMC + d] = q;
        inS[(SDIM + d) * PITCH + r] = z + (q - z);
    }
    __syncthreads();

    gemm_tile(inS, DECIN, dw1, db1, hA, true, warp, lane);
    __syncthreads();
    gemm_tile(hA, DIMC, dw2, db2, hB, true, warp, lane);
    __syncthreads();

    {
        int r  = tid & 63;
        int c  = (tid >> 6) * 2;
        float a0 = 0.f, a1 = 0.f;
        #pragma unroll 4
        for (int d = 0; d < DIMC; d++) {
            float h = hB[d * PITCH + r];
            a0 = fmaf(h, dw3[d * XD + c],     a0);
            a1 = fmaf(h, dw3[d * XD + c + 1], a1);
        }
        out_xt[(size_t)(rbase + r) * XD + c]     = a0 + db3[c];
        out_xt[(size_t)(rbase + r) * XD + c + 1] = a1 + db3[c + 1];
    }
}

// ---------------- launch ----------------
extern "C" void kernel_launch(void* const* d_in, const int* in_sizes, int n_in,
                              void* d_out, int out_size) {
    const float* state = (const float*)d_in[0];
    const float* x     = (const float*)d_in[1];
    const float* cb    = (const float*)d_in[2];
    const float* ew1   = (const float*)d_in[3];
    const float* eb1   = (const float*)d_in[4];
    const float* ew2   = (const float*)d_in[5];
    const float* eb2   = (const float*)d_in[6];
    const float* ew3   = (const float*)d_in[7];
    const float* eb3   = (const float*)d_in[8];
    const float* dw1   = (const float*)d_in[9];
    const float* db1   = (const float*)d_in[10];
    const float* dw2   = (const float*)d_in[11];
    const float* db2   = (const float*)d_in[12];
    const float* dw3   = (const float*)d_in[13];
    const float* db3   = (const float*)d_in[14];

    const int nrows = in_sizes[0] / SDIM;   // 262144

    size_t smemA = (size_t)(ENCIN + 2 * DIMC) * PITCH * sizeof(float);
    size_t smemC = (size_t)(DECIN + 2 * DIMC) * PITCH * sizeof(float);
    static bool attrs_set = false;
    if (!attrs_set) {
        cudaFuncSetAttribute((const void*)enc_kernel, cudaFuncAttributeMaxDynamicSharedMemorySize, (int)smemA);
        cudaFuncSetAttribute((const void*)vq_kernel,  cudaFuncAttributeMaxDynamicSharedMemorySize, VQ_SMEM);
        cudaFuncSetAttribute((const void*)dec_kernel, cudaFuncAttributeMaxDynamicSharedMemorySize, (int)smemC);
        attrs_set = true;
    }

    vq_prep<<<KC, DIMC>>>(cb);
    enc_kernel<<<nrows / ROWS, NTHR, smemA>>>(state, x, ew1, eb1, ew2, eb2, ew3, eb3,
                                              (float*)d_out, nrows);
    vq_kernel<<<nrows / VROWS, VTHR, VQ_SMEM>>>(cb, (float*)d_out, nrows);
    dec_kernel<<<nrows / ROWS, NTHR, smemC>>>(state, cb, dw1, db1, dw2, db2, dw3, db3,
                                              (float*)d_out, nrows);
}

// round 5
// speedup vs baseline: 1.3823x; 1.1860x over previous
#include <cuda_runtime.h>
#include <cuda_fp16.h>
#include <cstdint>

typedef unsigned long long u64;
typedef unsigned int u32;

#define PITCH   68
#define ROWS    64
#define NTHR    256
#define DIMC    128
#define KC      1024
#define SDIM    256
#define XD      8
#define ENCIN   264
#define DECIN   384
#define BTOT    262144

#define VROWS   128
#define VTHR    512
#define NCHUNK  8
#define CHN     128
#define CAND_MAX 16
#define APW     68           // u32 words pitch for fp16 tiles (row = 64 words + pad)
#define DOTSCALE 0.0009765625f   // 2^-10, exact

// ---------------- scratch globals ----------------
__device__ float   g_cnorm[KC];
__device__ __half  g_ch16[KC * DIMC];     // fp16(codebook * 1024)
__device__ float   g_ze[(size_t)BTOT * DIMC];
__device__ float   g_znorm[BTOT];
__device__ float   g_zabs[BTOT];
__device__ int     g_idx[BTOT];

// ---------------- prep: cnorm (fp32) + scaled fp16 codebook ----------------
__global__ void vq_prep(const float* __restrict__ cb) {
    int j = blockIdx.x;
    int d = threadIdx.x;
    float v = cb[j * DIMC + d];
    g_ch16[j * DIMC + d] = __float2half_rn(v * 1024.0f);
    __shared__ float red[DIMC];
    red[d] = v * v;
    __syncthreads();
    #pragma unroll
    for (int s = 64; s > 0; s >>= 1) {
        if (d < s) red[d] += red[d + s];
        __syncthreads();
    }
    if (d == 0) g_cnorm[j] = red[0];
}

// ---------------- packed f32x2 helpers ----------------
__device__ __forceinline__ u64 dup2(float w) {
    u64 r; unsigned u = __float_as_uint(w);
    asm("mov.b64 %0, {%1, %1};" : "=l"(r) : "r"(u));
    return r;
}
__device__ __forceinline__ void ffma2(u64& d, u64 a, u64 b) {
    asm("fma.rn.f32x2 %0, %1, %2, %0;" : "+l"(d) : "l"(a), "l"(b));
}
__device__ __forceinline__ float2 unpk(u64 v) {
    unsigned lo, hi;
    asm("mov.b64 {%0, %1}, %2;" : "=r"(lo), "=r"(hi) : "l"(v));
    return make_float2(__uint_as_float(lo), __uint_as_float(hi));
}

// ---------------- fp32 gemm (accumulate + store split) ----------------
__device__ __forceinline__ void gemm_accum(
    const float* __restrict__ inS, int Kdim,
    const float* __restrict__ W, u64 (&acc)[4][4], int warp, int lane)
{
    const int r0 = warp * 8;
    const int c0 = lane * 4;
    #pragma unroll 4
    for (int k = 0; k < Kdim; k++) {
        const ulonglong2 aA = *(const ulonglong2*)(inS + k * PITCH + r0);
        const ulonglong2 aB = *(const ulonglong2*)(inS + k * PITCH + r0 + 4);
        const float4 w = *(const float4*)(W + (size_t)k * DIMC + c0);
        const u64 wd[4] = {dup2(w.x), dup2(w.y), dup2(w.z), dup2(w.w)};
        const u64 av[4] = {aA.x, aA.y, aB.x, aB.y};
        #pragma unroll
        for (int i = 0; i < 4; i++) {
            ffma2(acc[i][0], av[i], wd[0]);
            ffma2(acc[i][1], av[i], wd[1]);
            ffma2(acc[i][2], av[i], wd[2]);
            ffma2(acc[i][3], av[i], wd[3]);
        }
    }
}
__device__ __forceinline__ void gemm_store(
    u64 (&acc)[4][4], const float* __restrict__ bias,
    float* __restrict__ outS, bool relu, int warp, int lane)
{
    const int r0 = warp * 8;
    const int c0 = lane * 4;
    const float4 b = *(const float4*)(bias + c0);
    const float bv[4] = {b.x, b.y, b.z, b.w};
    #pragma unroll
    for (int j = 0; j < 4; j++) {
        float o[8];
        #pragma unroll
        for (int i = 0; i < 4; i++) {
            float2 p = unpk(acc[i][j]);
            float v0 = p.x + bv[j];
            float v1 = p.y + bv[j];
            o[2 * i]     = relu ? fmaxf(v0, 0.f) : v0;
            o[2 * i + 1] = relu ? fmaxf(v1, 0.f) : v1;
        }
        *(float4*)(outS + (c0 + j) * PITCH + r0)     = make_float4(o[0], o[1], o[2], o[3]);
        *(float4*)(outS + (c0 + j) * PITCH + r0 + 4) = make_float4(o[4], o[5], o[6], o[7]);
    }
}

// ---------------- encoder (fp32, 2 CTAs/SM via buffer aliasing) --------------
__global__ void __launch_bounds__(NTHR, 2) enc_kernel(
    const float* __restrict__ state, const float* __restrict__ x,
    const float* __restrict__ ew1, const float* __restrict__ eb1,
    const float* __restrict__ ew2, const float* __restrict__ eb2,
    const float* __restrict__ ew3, const float* __restrict__ eb3,
    float* __restrict__ out, int nrows)
{
    extern __shared__ float sm[];
    float* X  = sm;                      // [ENCIN][PITCH]; reused as hB
    float* hA = sm + ENCIN * PITCH;      // [DIMC][PITCH]

    const int tid  = threadIdx.x;
    const int warp = tid >> 5, lane = tid & 31;
    const int rbase = blockIdx.x * ROWS;

    for (int e = tid; e < ROWS * SDIM; e += NTHR) {
        int r = e >> 8, k = e & 255;
        X[k * PITCH + r] = state[(size_t)(rbase + r) * SDIM + k];
    }
    for (int e = tid; e < ROWS * XD; e += NTHR) {
        int r = e >> 3, k = e & 7;
        X[(SDIM + k) * PITCH + r] = x[(size_t)(rbase + r) * XD + k];
    }
    __syncthreads();

    u64 acc[4][4];
    #pragma unroll
    for (int i = 0; i < 4; i++) { acc[i][0]=0; acc[i][1]=0; acc[i][2]=0; acc[i][3]=0; }
    gemm_accum(X, ENCIN, ew1, acc, warp, lane);
    gemm_store(acc, eb1, hA, true, warp, lane);        // h1 -> hA
    __syncthreads();

    #pragma unroll
    for (int i = 0; i < 4; i++) { acc[i][0]=0; acc[i][1]=0; acc[i][2]=0; acc[i][3]=0; }
    gemm_accum(hA, DIMC, ew2, acc, warp, lane);
    gemm_store(acc, eb2, X, true, warp, lane);         // h2 -> X (alias)
    __syncthreads();

    #pragma unroll
    for (int i = 0; i < 4; i++) { acc[i][0]=0; acc[i][1]=0; acc[i][2]=0; acc[i][3]=0; }
    gemm_accum(X, DIMC, ew3, acc, warp, lane);
    gemm_store(acc, eb3, hA, false, warp, lane);       // z_e -> hA
    __syncthreads();

    if (tid < ROWS) {
        float s = 0.f, a = 0.f;
        #pragma unroll 4
        for (int d = 0; d < DIMC; d++) {
            float z = hA[d * PITCH + tid];
            s = fmaf(z, z, s);
            a += fabsf(z);
        }
        g_znorm[rbase + tid] = s;
        g_zabs[rbase + tid]  = a;
    }

    const size_t B = (size_t)nrows;
    float* out_ze = out + B * XD;
    for (int e = tid; e < ROWS * DIMC; e += NTHR) {
        int r = e >> 7, d = e & 127;
        float z = hA[d * PITCH + r];
        out_ze[(size_t)(rbase + r) * DIMC + d] = z;
        g_ze[(size_t)(rbase + r) * DIMC + d]   = z;
    }
}

// ---------------- fp16 mma helper ----------------
__device__ __forceinline__ void mma16816(float* d, u32 a0, u32 a1, u32 a2, u32 a3,
                                         u32 b0, u32 b1) {
    asm volatile(
        "mma.sync.aligned.m16n8k16.row.col.f32.f16.f16.f32 "
        "{%0,%1,%2,%3}, {%4,%5,%6,%7}, {%8,%9}, {%0,%1,%2,%3};"
        : "+f"(d[0]), "+f"(d[1]), "+f"(d[2]), "+f"(d[3])
        : "r"(a0), "r"(a1), "r"(a2), "r"(a3), "r"(b0), "r"(b1));
}

__device__ __forceinline__ u32 fmap(float f) {
    u32 u = __float_as_uint(f);
    return (u & 0x80000000u) ? ~u : (u | 0x80000000u);
}
__device__ __forceinline__ float finv(u32 m) {
    u32 u = (m & 0x80000000u) ? (m ^ 0x80000000u) : ~m;
    return __uint_as_float(u);
}

// ---------------- VQ kernel (fp16 2-term + exact fp32 refine) ----------------
// smem: 0 finalS u64[128] | 1024 cnS f32[1024] | 5120 margS f32[128]
//       5632 bestU u32[128] | 6144 cntS u32[128] | 6656 candS u32[128*16]
//       14848 zhS u32[128*68] | 49664 zlS u32[128*68] | 84480 chS[2] u32[2*128*68]
#define VQ_SMEM 154112

__global__ void __launch_bounds__(VTHR, 1) vq_kernel(
    const float* __restrict__ cb, float* __restrict__ out, int nrows)
{
    extern __shared__ char smc[];
    u64*   finalS = (u64*)(smc);
    float* cnS    = (float*)(smc + 1024);
    float* margS  = (float*)(smc + 5120);
    u32*   bestU  = (u32*)(smc + 5632);
    u32*   cntS   = (u32*)(smc + 6144);
    u32*   candS  = (u32*)(smc + 6656);
    u32*   zhS    = (u32*)(smc + 14848);
    u32*   zlS    = (u32*)(smc + 49664);
    u32*   chB0   = (u32*)(smc + 84480);
    u32*   chB1   = (u32*)(smc + 84480 + 34816);

    const int tid  = threadIdx.x;
    const int wid  = tid >> 5, lane = tid & 31;
    const int g    = lane >> 2, tg = lane & 3;
    const int rbase = blockIdx.x * VROWS;

    const int mbase = (wid >> 1) * 16;      // 8 M-tiles
    const int nhalf = (wid & 1) * 64;       // 2 N-halves

    // ---- init ----
    for (int i = tid; i < KC; i += VTHR) cnS[i] = g_cnorm[i];
    for (int i = tid; i < VROWS; i += VTHR) {
        bestU[i]  = 0xFFFFFFFFu;
        finalS[i] = ~0ull;
        cntS[i]   = 0u;
        margS[i]  = g_zabs[rbase + i] * 2.5e-6f + 1.0e-5f;
    }

    // ---- stage A: z_e -> (zh, zl) fp16 pairs ----
    for (int i = tid; i < VROWS * 64; i += VTHR) {
        int r = i >> 6, c = i & 63;
        float2 z = *(const float2*)(g_ze + (size_t)(rbase + r) * DIMC + c * 2);
        __half h0 = __float2half_rn(z.x);
        __half h1 = __float2half_rn(z.y);
        __half l0 = __float2half_rn(z.x - __half2float(h0));
        __half l1 = __float2half_rn(z.y - __half2float(h1));
        __half2 hp(h0, h1), lp(l0, l1);
        zhS[r * APW + c] = *(u32*)&hp;
        zlS[r * APW + c] = *(u32*)&lp;
    }

    // ---- stage B chunk 0 ----
    {
        const uint4* src = (const uint4*)(g_ch16);
        #pragma unroll
        for (int t = 0; t < 4; t++) {
            int i = t * VTHR + tid;                 // i in [0, 2048)
            uint4 v = src[i];
            *(uint4*)(chB0 + (i >> 4) * APW + (i & 15) * 4) = v;
        }
    }
    __syncthreads();

    const int r1 = mbase + g, r2 = r1 + 8;
    const float marg1 = margS[r1], marg2 = margS[r2];

    float dacc[8][4];

    for (int q = 0; q < NCHUNK; q++) {
        u32* chD = (q & 1) ? chB1 : chB0;
        u32* chN = (q & 1) ? chB0 : chB1;

        // prefetch next chunk into regs (overlaps with MMA)
        uint4 pf0, pf1, pf2, pf3;
        if (q < NCHUNK - 1) {
            const uint4* src = (const uint4*)(g_ch16 + (size_t)(q + 1) * CHN * DIMC);
            pf0 = src[0 * VTHR + tid];
            pf1 = src[1 * VTHR + tid];
            pf2 = src[2 * VTHR + tid];
            pf3 = src[3 * VTHR + tid];
        }

        #pragma unroll
        for (int nt = 0; nt < 8; nt++) {
            dacc[nt][0] = 0.f; dacc[nt][1] = 0.f; dacc[nt][2] = 0.f; dacc[nt][3] = 0.f;
        }

        // single pass: (zh + zl) * ch, B-fragments shared
        #pragma unroll
        for (int kt = 0; kt < 8; kt++) {
            const int ka = kt * 8 + tg;
            const u32 h0 = zhS[r1 * APW + ka];
            const u32 h1 = zhS[r2 * APW + ka];
            const u32 h2 = zhS[r1 * APW + ka + 4];
            const u32 h3 = zhS[r2 * APW + ka + 4];
            const u32 l0 = zlS[r1 * APW + ka];
            const u32 l1 = zlS[r2 * APW + ka];
            const u32 l2 = zlS[r1 * APW + ka + 4];
            const u32 l3 = zlS[r2 * APW + ka + 4];
            #pragma unroll
            for (int nt = 0; nt < 8; nt++) {
                const int w = (nhalf + nt * 8 + g) * APW + ka;
                const u32 b0 = chD[w], b1 = chD[w + 4];
                mma16816(dacc[nt], h0, h1, h2, h3, b0, b1);
                mma16816(dacc[nt], l0, l1, l2, l3, b0, b1);
            }
        }

        // ---- epilogue: no barriers; thr from own atomicMin is a valid upper bound
        u32 min1 = 0xFFFFFFFFu, min2 = 0xFFFFFFFFu;
        #pragma unroll
        for (int nt = 0; nt < 8; nt++) {
            const int jb = q * CHN + nhalf + nt * 8 + 2 * tg;
            float s0 = fmaf(dacc[nt][0], -2.0f * DOTSCALE, cnS[jb]);
            float s1 = fmaf(dacc[nt][1], -2.0f * DOTSCALE, cnS[jb + 1]);
            float s2 = fmaf(dacc[nt][2], -2.0f * DOTSCALE, cnS[jb]);
            float s3 = fmaf(dacc[nt][3], -2.0f * DOTSCALE, cnS[jb + 1]);
            dacc[nt][0] = s0; dacc[nt][1] = s1; dacc[nt][2] = s2; dacc[nt][3] = s3;
            min1 = min(min1, min(fmap(s0), fmap(s1)));
            min2 = min(min2, min(fmap(s2), fmap(s3)));
        }
        u32 o1 = atomicMin(&bestU[r1], min1);
        u32 o2 = atomicMin(&bestU[r2], min2);
        const float thr1 = finv(min(o1, min1)) + marg1;
        const float thr2 = finv(min(o2, min2)) + marg2;
        #pragma unroll
        for (int nt = 0; nt < 8; nt++) {
            const int jb = q * CHN + nhalf + nt * 8 + 2 * tg;
            if (dacc[nt][0] <= thr1) {
                u32 p = atomicAdd(&cntS[r1], 1u);
                if (p < CAND_MAX) candS[r1 * CAND_MAX + p] = (u32)jb;
            }
            if (dacc[nt][1] <= thr1) {
                u32 p = atomicAdd(&cntS[r1], 1u);
                if (p < CAND_MAX) candS[r1 * CAND_MAX + p] = (u32)(jb + 1);
            }
            if (dacc[nt][2] <= thr2) {
                u32 p = atomicAdd(&cntS[r2], 1u);
                if (p < CAND_MAX) candS[r2 * CAND_MAX + p] = (u32)jb;
            }
            if (dacc[nt][3] <= thr2) {
                u32 p = atomicAdd(&cntS[r2], 1u);
                if (p < CAND_MAX) candS[r2 * CAND_MAX + p] = (u32)(jb + 1);
            }
        }

        // store prefetched chunk into the other buffer
        if (q < NCHUNK - 1) {
            int i0 = 0 * VTHR + tid;
            int i1 = 1 * VTHR + tid;
            int i2 = 2 * VTHR + tid;
            int i3 = 3 * VTHR + tid;
            *(uint4*)(chN + (i0 >> 4) * APW + (i0 & 15) * 4) = pf0;
            *(uint4*)(chN + (i1 >> 4) * APW + (i1 & 15) * 4) = pf1;
            *(uint4*)(chN + (i2 >> 4) * APW + (i2 & 15) * 4) = pf2;
            *(uint4*)(chN + (i3 >> 4) * APW + (i3 & 15) * 4) = pf3;
        }
        __syncthreads();
    }

    // ---- exact fp32 refine (reference order); full-scan fallback on overflow
    {
        const int rr = tid >> 2, c4 = tid & 3;
        const float zn = g_znorm[rbase + rr];
        const float* zp = g_ze + (size_t)(rbase + rr) * DIMC;
        int cnt = (int)cntS[rr];
        if (cnt <= CAND_MAX) {
            for (int c = c4; c < cnt; c += 4) {
                int j = (int)candS[rr * CAND_MAX + c];
                const float* cp = cb + (size_t)j * DIMC;
                float dot = 0.f;
                #pragma unroll 8
                for (int d = 0; d < DIMC; d++) dot = fmaf(zp[d], cp[d], dot);
                float dvv = (zn - 2.0f * dot) + cnS[j];
                u64 key = ((u64)fmap(dvv) << 32) | (u32)j;
                atomicMin(&finalS[rr], key);
            }
        } else {
            for (int j = c4; j < KC; j += 4) {
                const float* cp = cb + (size_t)j * DIMC;
                float dot = 0.f;
                #pragma unroll 8
                for (int d = 0; d < DIMC; d++) dot = fmaf(zp[d], cp[d], dot);
                float dvv = (zn - 2.0f * dot) + cnS[j];
                u64 key = ((u64)fmap(dvv) << 32) | (u32)j;
                atomicMin(&finalS[rr], key);
            }
        }
    }
    __syncthreads();

    if (tid < VROWS) {
        int idx = (int)(finalS[tid] & 0xFFFFFFFFull);
        g_idx[rbase + tid] = idx;
        float* out_id = out + (size_t)nrows * XD + (size_t)nrows * DIMC * 2;
        out_id[rbase + tid] = (float)idx;
    }
}

// ---------------- decoder (fp32, K-split staging -> 2 CTAs/SM) ----------------
__global__ void __launch_bounds__(NTHR, 2) dec_kernel(
    const float* __restrict__ state, const float* __restrict__ cb,
    const float* __restrict__ dw1, const float* __restrict__ db1,
    const float* __restrict__ dw2, const float* __restrict__ db2,
    const float* __restrict__ dw3, const float* __restrict__ db3,
    float* __restrict__ out, int nrows)
{
    extern __shared__ float sm[];
    float* X  = sm;                      // [SDIM][PITCH] staging; later h2
    float* hA = sm + SDIM * PITCH;       // [DIMC][PITCH]

    const int tid  = threadIdx.x;
    const int warp = tid >> 5, lane = tid & 31;
    const int rbase = blockIdx.x * ROWS;

    const size_t B = (size_t)nrows;
    float* out_xt = out;
    float* out_zq = out + B * XD + B * (size_t)DIMC;

    // stage state (k = 0..255)
    for (int e = tid; e < ROWS * SDIM; e += NTHR) {
        int r = e >> 8, k = e & 255;
        X[k * PITCH + r] = state[(size_t)(rbase + r) * SDIM + k];
    }
    __syncthreads();

    u64 acc[4][4];
    #pragma unroll
    for (int i = 0; i < 4; i++) { acc[i][0]=0; acc[i][1]=0; acc[i][2]=0; acc[i][3]=0; }
    gemm_accum(X, SDIM, dw1, acc, warp, lane);        // partial K = 0..255
    __syncthreads();

    // restage z_q straight-through (k = 256..383), write z_q output
    for (int e = tid; e < ROWS * DIMC; e += NTHR) {
        int r = e >> 7, d = e & 127;
        float z = g_ze[(size_t)(rbase + r) * DIMC + d];
        float q = cb[(size_t)g_idx[rbase + r] * DIMC + d];
        out_zq[(size_t)(rbase + r) * DIMC + d] = q;
        X[d * PITCH + r] = z + (q - z);
    }
    __syncthreads();

    gemm_accum(X, DIMC, dw1 + (size_t)SDIM * DIMC, acc, warp, lane);  // K = 256..383
    gemm_store(acc, db1, hA, true, warp, lane);       // h1 -> hA
    __syncthreads();

    #pragma unroll
    for (int i = 0; i < 4; i++) { acc[i][0]=0; acc[i][1]=0; acc[i][2]=0; acc[i][3]=0; }
    gemm_accum(hA, DIMC, dw2, acc, warp, lane);
    gemm_store(acc, db2, X, true, warp, lane);        // h2 -> X (alias)
    __syncthreads();

    // final layer: [64 rows][8 cols]
    {
        int r  = tid & 63;
        int c  = (tid >> 6) * 2;
        float a0 = 0.f, a1 = 0.f;
        #pragma unroll 4
        for (int d = 0; d < DIMC; d++) {
            float h = X[d * PITCH + r];
            a0 = fmaf(h, dw3[d * XD + c],     a0);
            a1 = fmaf(h, dw3[d * XD + c + 1], a1);
        }
        out_xt[(size_t)(rbase + r) * XD + c]     = a0 + db3[c];
        out_xt[(size_t)(rbase + r) * XD + c + 1] = a1 + db3[c + 1];
    }
}

// ---------------- launch ----------------
extern "C" void kernel_launch(void* const* d_in, const int* in_sizes, int n_in,
                              void* d_out, int out_size) {
    const float* state = (const float*)d_in[0];
    const float* x     = (const float*)d_in[1];
    const float* cb    = (const float*)d_in[2];
    const float* ew1   = (const float*)d_in[3];
    const float* eb1   = (const float*)d_in[4];
    const float* ew2   = (const float*)d_in[5];
    const float* eb2   = (const float*)d_in[6];
    const float* ew3   = (const float*)d_in[7];
    const float* eb3   = (const float*)d_in[8];
    const float* dw1   = (const float*)d_in[9];
    const float* db1   = (const float*)d_in[10];
    const float* dw2   = (const float*)d_in[11];
    const float* db2   = (const float*)d_in[12];
    const float* dw3   = (const float*)d_in[13];
    const float* db3   = (const float*)d_in[14];

    const int nrows = in_sizes[0] / SDIM;   // 262144

    size_t smemA = (size_t)(ENCIN + DIMC) * PITCH * sizeof(float);   // 106.6 KB
    size_t smemC = (size_t)(SDIM + DIMC)  * PITCH * sizeof(float);   // 104.4 KB
    static bool attrs_set = false;
    if (!attrs_set) {
        cudaFuncSetAttribute((const void*)enc_kernel, cudaFuncAttributeMaxDynamicSharedMemorySize, (int)smemA);
        cudaFuncSetAttribute((const void*)vq_kernel,  cudaFuncAttributeMaxDynamicSharedMemorySize, VQ_SMEM);
        cudaFuncSetAttribute((const void*)dec_kernel, cudaFuncAttributeMaxDynamicSharedMemorySize, (int)smemC);
        attrs_set = true;
    }

    vq_prep<<<KC, DIMC>>>(cb);
    enc_kernel<<<nrows / ROWS, NTHR, smemA>>>(state, x, ew1, eb1, ew2, eb2, ew3, eb3,
                                              (float*)d_out, nrows);
    vq_kernel<<<nrows / VROWS, VTHR, VQ_SMEM>>>(cb, (float*)d_out, nrows);
    dec_kernel<<<nrows / ROWS, NTHR, smemC>>>(state, cb, dw1, db1, dw2, db2, dw3, db3,
                                              (float*)d_out, nrows);
}